// round 10
// baseline (speedup 1.0000x reference)
#include <cuda_runtime.h>
#include <math.h>
#include <stdint.h>

#define LLATT 16
#define UU    512
#define NB    4            // batches per group
#define CL    2            // CTAs per cluster (unit split)
#define USL   256          // units per CTA
#define NTHR  256
#define NGRP  64
#define NCTA  128

typedef unsigned long long ull;

struct SM {
    ull   hbuf[2][UU][2];        // [buf][global unit][bpair]       16 KB
    ull   states[8][UU][2];      // last 8 scan-positions            64 KB
    ull   vrow[LLATT][USL][2];   // vertical term per column         64 KB
    ull   pred[128][2][2];       // k-half partials [tu][unit][bpair] 4 KB
    float winh[2][UU];
    float winv[2][UU];
    float wout[UU][2];
    float bcarry[UU];
    float zred[4][NB][2];        // warp-level logit partials
    ull   zp[2][NB];             // peer z-partials, double buffered
    float logp[NB];
    float bout0, bout1;
    int   xs[NB][LLATT * LLATT];
    ull   bar1;
};

__device__ __forceinline__ ull pk2(float lo, float hi) {
    ull r; asm("mov.b64 %0, {%1, %2};" : "=l"(r) : "f"(lo), "f"(hi)); return r;
}
__device__ __forceinline__ void upk2(ull v, float& lo, float& hi) {
    asm("mov.b64 {%0, %1}, %2;" : "=f"(lo), "=f"(hi) : "l"(v));
}
__device__ __forceinline__ void fma2(ull& acc, ull a, ull b) {
    asm("fma.rn.f32x2 %0, %1, %2, %0;" : "+l"(acc) : "l"(a), "l"(b));
}
__device__ __forceinline__ ull add2(ull a, ull b) {
    ull r; asm("add.rn.f32x2 %0, %1, %2;" : "=l"(r) : "l"(a), "l"(b)); return r;
}
__device__ __forceinline__ uint32_t smem_u32(const void* p) {
    return (uint32_t)__cvta_generic_to_shared(p);
}
__device__ __forceinline__ uint32_t mapa_rank(uint32_t a, uint32_t r) {
    uint32_t o; asm("mapa.shared::cluster.u32 %0, %1, %2;" : "=r"(o) : "r"(a), "r"(r));
    return o;
}
__device__ __forceinline__ void st_cl64(uint32_t addr, ull v) {
    asm volatile("st.shared::cluster.b64 [%0], %1;" :: "r"(addr), "l"(v) : "memory");
}
__device__ __forceinline__ void mbar_init(uint32_t addr, uint32_t cnt) {
    asm volatile("mbarrier.init.shared.b64 [%0], %1;" :: "r"(addr), "r"(cnt) : "memory");
}
__device__ __forceinline__ void mbar_arrive_remote(uint32_t addr) {
    asm volatile("mbarrier.arrive.release.cluster.shared::cluster.b64 _, [%0];"
                 :: "r"(addr) : "memory");
}
__device__ __forceinline__ void mbar_wait_parity(uint32_t addr, uint32_t parity) {
    asm volatile(
        "{\n\t.reg .pred P;\n\t"
        "WLP_%=:\n\t"
        "mbarrier.try_wait.parity.acquire.cluster.shared::cta.b64 P, [%0], %1, 0x989680;\n\t"
        "@P bra.uni WDN_%=;\n\t"
        "bra.uni WLP_%=;\n\t"
        "WDN_%=:\n\t}"
        :: "r"(addr), "r"(parity) : "memory");
}
#define CLUSTER_ARRIVE() asm volatile("barrier.cluster.arrive.aligned;" ::: "memory")
#define CLUSTER_WAIT()   asm volatile("barrier.cluster.wait.aligned;"   ::: "memory")

__global__ void __launch_bounds__(NTHR, 1) __cluster_dims__(CL, 1, 1)
rnn2d_kernel(const int* __restrict__ x,
             const float* __restrict__ Winh, const float* __restrict__ Winv,
             const float* __restrict__ Wch,  const float* __restrict__ bch,
             const float* __restrict__ Wcv,
             const float* __restrict__ Wout, const float* __restrict__ bout,
             float* __restrict__ out)
{
    extern __shared__ char smraw[];
    SM& sm = *reinterpret_cast<SM*>(smraw);
    const int tid = threadIdx.x;
    uint32_t rank;
    asm("mov.u32 %0, %%cluster_ctarank;" : "=r"(rank));
    const int grp = blockIdx.x >> 1;

    // ---------------- prologue ----------------
    for (int idx = tid; idx < 2 * UU; idx += NTHR) {
        ((float*)sm.winh)[idx] = Winh[idx];
        ((float*)sm.winv)[idx] = Winv[idx];
        ((float*)sm.wout)[idx] = Wout[idx];
    }
    for (int idx = tid; idx < UU; idx += NTHR) sm.bcarry[idx] = bch[idx];
    for (int idx = tid; idx < NB * LLATT * LLATT; idx += NTHR)
        ((int*)sm.xs)[idx] = x[grp * NB * LLATT * LLATT + idx];
    if (tid < NB) sm.logp[tid] = 0.f;
    if (tid == 0) {
        sm.bout0 = bout[0]; sm.bout1 = bout[1];
        mbar_init(smem_u32(&sm.bar1), 132);   // 128 h-pushers + 4 z-pushers
    }
    __syncthreads();
    CLUSTER_ARRIVE(); CLUSTER_WAIT();          // publish mbarrier init

    const int khalf = tid >> 7;                // 0: k 0-255 (writers), 1: k 256-511
    const int tu    = tid & 127;
    const int ug0   = (int)rank * USL + 2 * tu;  // global unit pair

    const uint32_t bar_loc  = smem_u32(&sm.bar1);
    const uint32_t bar_rem  = mapa_rank(bar_loc, rank ^ 1u);
    const uint32_t hbuf_rem = mapa_rank(smem_u32(&sm.hbuf[0][0][0]), rank ^ 1u);
    const uint32_t st_rem   = mapa_rank(smem_u32(&sm.states[0][0][0]), rank ^ 1u);
    const uint32_t zp_rem   = mapa_rank(smem_u32(&sm.zp[0][0]), rank ^ 1u);

    const float2* __restrict__ WchP =
        reinterpret_cast<const float2*>(Wch + (size_t)(khalf * 256) * UU + ug0);
    const float2* __restrict__ WcvP =
        reinterpret_cast<const float2*>(Wcv + (size_t)0) + (int)rank * 128 + tu;

    int n = 0;
    for (int i = 0; i < LLATT; ++i) {
        const int d = (i & 1) ? -1 : 1;
        for (int j = 0; j < LLATT; ++j, ++n) {
            const int c   = (d == 1) ? j : (LLATT - 1 - j);
            const int buf = n & 1;

            // ---- half-row vertical GEMM events (31 total) ----
            if ((j == 8 && i < 15) || (j == 0 && i > 0)) {
                __syncthreads();
                const int i_src = (j == 8) ? i : i - 1;
                const int p0    = (j == 8) ? 0 : 8;
                ull A[8][2][2];
#pragma unroll
                for (int p = 0; p < 8; ++p)
#pragma unroll
                    for (int q = 0; q < 2; ++q) { A[p][q][0] = 0ull; A[p][q][1] = 0ull; }
                float2 wb[2][8];
#pragma unroll
                for (int q = 0; q < 8; ++q) wb[0][q] = WcvP[(khalf * 256 + q) * 256];
#pragma unroll 1
                for (int kk = 0; kk < 256; kk += 8) {
                    const int cb = (kk >> 3) & 1;
                    if (kk + 8 < 256) {
#pragma unroll
                        for (int q = 0; q < 8; ++q)
                            wb[cb ^ 1][q] = WcvP[(khalf * 256 + kk + 8 + q) * 256];
                    }
#pragma unroll
                    for (int q = 0; q < 8; ++q) {
                        const int k = khalf * 256 + kk + q;
                        const float2 w = wb[cb][q];
                        const ull wx = pk2(w.x, w.x);
                        const ull wy = pk2(w.y, w.y);
#pragma unroll
                        for (int p = 0; p < 8; ++p) {
                            const ulonglong2 sv = *(const ulonglong2*)&sm.states[p][k][0];
                            fma2(A[p][0][0], sv.x, wx); fma2(A[p][0][1], sv.y, wx);
                            fma2(A[p][1][0], sv.x, wy); fma2(A[p][1][1], sv.y, wy);
                        }
                    }
                }
                const int lu0 = 2 * tu;
                if (khalf == 0) {
#pragma unroll
                    for (int p = 0; p < 8; ++p) {
                        const int col = (i_src & 1) ? 15 - (p0 + p) : (p0 + p);
                        sm.vrow[col][lu0][0] = A[p][0][0];
                        sm.vrow[col][lu0][1] = A[p][0][1];
                        sm.vrow[col][lu0 + 1][0] = A[p][1][0];
                        sm.vrow[col][lu0 + 1][1] = A[p][1][1];
                    }
                }
                __syncthreads();
                if (khalf == 1) {
#pragma unroll
                    for (int p = 0; p < 8; ++p) {
                        const int col = (i_src & 1) ? 15 - (p0 + p) : (p0 + p);
                        sm.vrow[col][lu0][0] = add2(sm.vrow[col][lu0][0], A[p][0][0]);
                        sm.vrow[col][lu0][1] = add2(sm.vrow[col][lu0][1], A[p][0][1]);
                        sm.vrow[col][lu0 + 1][0] = add2(sm.vrow[col][lu0 + 1][0], A[p][1][0]);
                        sm.vrow[col][lu0 + 1][1] = add2(sm.vrow[col][lu0 + 1][1], A[p][1][1]);
                    }
                }
                __syncthreads();
                CLUSTER_ARRIVE(); CLUSTER_WAIT();   // fence GEMM vs slot reuse
            }

            // ---- h @ W_carry_h over my k-half (skip at scan start) ----
            ull a00 = 0ull, a01 = 0ull, a10 = 0ull, a11 = 0ull;
            if (j > 0) {
                const int kbase = khalf * 256;
                float2 wb[2][8];
#pragma unroll
                for (int q = 0; q < 8; ++q) wb[0][q] = WchP[q * 256];
#pragma unroll 1
                for (int kk = 0; kk < 256; kk += 8) {
                    const int cb = (kk >> 3) & 1;
                    if (kk + 8 < 256) {
#pragma unroll
                        for (int q = 0; q < 8; ++q)
                            wb[cb ^ 1][q] = WchP[(kk + 8 + q) * 256];
                    }
#pragma unroll
                    for (int q = 0; q < 8; ++q) {
                        const int k = kbase + kk + q;
                        const ull h0 = sm.hbuf[buf ^ 1][k][0];
                        const ull h1 = sm.hbuf[buf ^ 1][k][1];
                        const float2 w = wb[cb][q];
                        const ull wx = pk2(w.x, w.x);
                        const ull wy = pk2(w.y, w.y);
                        fma2(a00, h0, wx); fma2(a01, h1, wx);
                        fma2(a10, h0, wy); fma2(a11, h1, wy);
                    }
                }
            }
            if (khalf == 1) {
                sm.pred[tu][0][0] = a00; sm.pred[tu][0][1] = a01;
                sm.pred[tu][1][0] = a10; sm.pred[tu][1][1] = a11;
            }
            __syncthreads();   // S1: partials visible

            // ---- reduce + inputs + elu + distribute + logit partials ----
            if (khalf == 0) {
                float v[2][4];
                upk2(a00, v[0][0], v[0][1]); upk2(a01, v[0][2], v[0][3]);
                upk2(a10, v[1][0], v[1][1]); upk2(a11, v[1][2], v[1][3]);
                if (j > 0) {
#pragma unroll
                    for (int q = 0; q < 2; ++q) {
                        float p0f, p1f;
                        upk2(sm.pred[tu][q][0], p0f, p1f);
                        v[q][0] += p0f; v[q][1] += p1f;
                        upk2(sm.pred[tu][q][1], p0f, p1f);
                        v[q][2] += p0f; v[q][3] += p1f;
                    }
                }
                if (i > 0) {
#pragma unroll
                    for (int q = 0; q < 2; ++q) {
                        float p0f, p1f;
                        upk2(sm.vrow[c][2 * tu + q][0], p0f, p1f);
                        v[q][0] += p0f; v[q][1] += p1f;
                        upk2(sm.vrow[c][2 * tu + q][1], p0f, p1f);
                        v[q][2] += p0f; v[q][3] += p1f;
                    }
                }
                int sh[NB], sv[NB];
                if (j > 0) {
                    const int cp = c - d;
#pragma unroll
                    for (int b = 0; b < NB; ++b) sh[b] = sm.xs[b][i * LLATT + cp];
                }
                if (i > 0) {
#pragma unroll
                    for (int b = 0; b < NB; ++b) sv[b] = sm.xs[b][(i - 1) * LLATT + c];
                }
                const int slot = j & 7;
#pragma unroll
                for (int q = 0; q < 2; ++q) {
                    const int u = ug0 + q;
                    const float base = sm.bcarry[u];
#pragma unroll
                    for (int b = 0; b < NB; ++b) {
                        float t = v[q][b] + base;
                        if (j > 0) t += sm.winh[sh[b]][u];
                        if (i > 0) t += sm.winv[sv[b]][u];
                        v[q][b] = t > 0.f ? t : expm1f(t);
                    }
                    const ull e0 = pk2(v[q][0], v[q][1]);
                    const ull e1 = pk2(v[q][2], v[q][3]);
                    sm.hbuf[buf][u][0] = e0;   sm.hbuf[buf][u][1] = e1;
                    sm.states[slot][u][0] = e0; sm.states[slot][u][1] = e1;
                    const uint32_t ho = (uint32_t)(((buf * UU + u) * 2) * 8);
                    st_cl64(hbuf_rem + ho,     e0);
                    st_cl64(hbuf_rem + ho + 8, e1);
                    const uint32_t so = (uint32_t)(((slot * UU + u) * 2) * 8);
                    st_cl64(st_rem + so,     e0);
                    st_cl64(st_rem + so + 8, e1);
                }
                mbar_arrive_remote(bar_rem);

                // ---- logit partials from registers (this CTA's 2 units) ----
                {
                    const float2 wo0 = *(const float2*)&sm.wout[ug0][0];
                    const float2 wo1 = *(const float2*)&sm.wout[ug0 + 1][0];
                    float pz0[NB], pz1[NB];
#pragma unroll
                    for (int b = 0; b < NB; ++b) {
                        pz0[b] = v[0][b] * wo0.x + v[1][b] * wo1.x;
                        pz1[b] = v[0][b] * wo0.y + v[1][b] * wo1.y;
                    }
#pragma unroll
                    for (int off = 16; off; off >>= 1) {
#pragma unroll
                        for (int b = 0; b < NB; ++b) {
                            pz0[b] += __shfl_down_sync(0xffffffffu, pz0[b], off);
                            pz1[b] += __shfl_down_sync(0xffffffffu, pz1[b], off);
                        }
                    }
                    if ((tu & 31) == 0) {
                        const int w = tu >> 5;
#pragma unroll
                        for (int b = 0; b < NB; ++b) {
                            sm.zred[w][b][0] = pz0[b];
                            sm.zred[w][b][1] = pz1[b];
                        }
                    }
                }
            }
            __syncthreads();              // S2: local h + zred visible

            // ---- z combine: 4 threads, push 8B each to peer, arrive ----
            float zl0 = 0.f, zl1 = 0.f;
            if (tid < NB) {
#pragma unroll
                for (int w = 0; w < 4; ++w) {
                    zl0 += sm.zred[w][tid][0];
                    zl1 += sm.zred[w][tid][1];
                }
                st_cl64(zp_rem + (uint32_t)((buf * NB + tid) * 8), pk2(zl0, zl1));
                mbar_arrive_remote(bar_rem);
            }
            mbar_wait_parity(bar_loc, (uint32_t)(n & 1));  // peer h + z arrived

            if (tid < NB) {
                float pz0, pz1;
                upk2(sm.zp[buf][tid], pz0, pz1);
                const float z0 = zl0 + pz0 + sm.bout0;
                const float z1 = zl1 + pz1 + sm.bout1;
                const int s = sm.xs[tid][i * LLATT + c];
                const float m = fmaxf(z0, z1);
                const float lse = m + logf(expf(z0 - m) + expf(z1 - m));
                sm.logp[tid] += (s ? z1 : z0) - lse;
            }
            // no barrier: next cell's GEMV reads hbuf[buf] (this cell's h),
            // complete locally at S2 and remotely per the mbar wait above.
        }
    }
    __syncthreads();
    if (rank == 0 && tid < NB) out[grp * NB + tid] = sm.logp[tid];
    CLUSTER_ARRIVE(); CLUSTER_WAIT();     // no CTA exits while peer may write DSMEM
}

extern "C" void kernel_launch(void* const* d_in, const int* in_sizes, int n_in,
                              void* d_out, int out_size)
{
    const int*   x    = (const int*)d_in[0];
    const float* Winh = (const float*)d_in[1];
    const float* Winv = (const float*)d_in[2];
    const float* Wch  = (const float*)d_in[3];
    const float* bch  = (const float*)d_in[4];
    const float* Wcv  = (const float*)d_in[5];
    const float* Wout = (const float*)d_in[6];
    const float* bout = (const float*)d_in[7];
    float* out = (float*)d_out;

    const int smem = (int)sizeof(SM);
    cudaFuncSetAttribute(rnn2d_kernel,
                         cudaFuncAttributeMaxDynamicSharedMemorySize, smem);
    rnn2d_kernel<<<NCTA, NTHR, smem>>>(x, Winh, Winv, Wch, bch, Wcv,
                                       Wout, bout, out);
}

// round 11
// speedup vs baseline: 1.4564x; 1.4564x over previous
#include <cuda_runtime.h>
#include <math.h>
#include <stdint.h>

#define LLATT 16
#define UU    512
#define NB    4            // batches per group
#define CL    2            // CTAs per cluster (unit split)
#define USL   256          // units per CTA
#define NTHR  256
#define NGRP  64
#define NCTA  128

typedef unsigned long long ull;

struct SM {
    ull    hbuf[2][UU][2];        // [buf][global unit][bpair]       16 KB
    ull    states[8][UU][2];      // last 8 scan positions            64 KB
    ull    vrow[LLATT][USL][2];   // vertical term per column         64 KB
    ull    pred[128][2][2];       // k-half partials                   4 KB
    float2 wstage[3][8][256];     // cp.async weight stages           48 KB
    float  winh[2][UU];
    float  winv[2][UU];
    float  wout[UU][2];
    float  bcarry[UU];
    float  z[NB][2];
    float  logp[NB];
    float  bout0, bout1;
    int    xs[NB][LLATT * LLATT];
    ull    bar1;
};

__device__ __forceinline__ ull pk2(float lo, float hi) {
    ull r; asm("mov.b64 %0, {%1, %2};" : "=l"(r) : "f"(lo), "f"(hi)); return r;
}
__device__ __forceinline__ void upk2(ull v, float& lo, float& hi) {
    asm("mov.b64 {%0, %1}, %2;" : "=f"(lo), "=f"(hi) : "l"(v));
}
__device__ __forceinline__ void fma2(ull& acc, ull a, ull b) {
    asm("fma.rn.f32x2 %0, %1, %2, %0;" : "+l"(acc) : "l"(a), "l"(b));
}
__device__ __forceinline__ ull add2(ull a, ull b) {
    ull r; asm("add.rn.f32x2 %0, %1, %2;" : "=l"(r) : "l"(a), "l"(b)); return r;
}
__device__ __forceinline__ uint32_t smem_u32(const void* p) {
    return (uint32_t)__cvta_generic_to_shared(p);
}
__device__ __forceinline__ uint32_t mapa_rank(uint32_t a, uint32_t r) {
    uint32_t o; asm("mapa.shared::cluster.u32 %0, %1, %2;" : "=r"(o) : "r"(a), "r"(r));
    return o;
}
__device__ __forceinline__ void st_cl64(uint32_t addr, ull v) {
    asm volatile("st.shared::cluster.b64 [%0], %1;" :: "r"(addr), "l"(v) : "memory");
}
__device__ __forceinline__ void mbar_init(uint32_t addr, uint32_t cnt) {
    asm volatile("mbarrier.init.shared.b64 [%0], %1;" :: "r"(addr), "r"(cnt) : "memory");
}
__device__ __forceinline__ void mbar_arrive_remote(uint32_t addr) {
    asm volatile("mbarrier.arrive.release.cluster.shared::cluster.b64 _, [%0];"
                 :: "r"(addr) : "memory");
}
__device__ __forceinline__ void mbar_wait_parity(uint32_t addr, uint32_t parity) {
    asm volatile(
        "{\n\t.reg .pred P;\n\t"
        "WLP_%=:\n\t"
        "mbarrier.try_wait.parity.acquire.cluster.shared::cta.b64 P, [%0], %1, 0x989680;\n\t"
        "@P bra.uni WDN_%=;\n\t"
        "bra.uni WLP_%=;\n\t"
        "WDN_%=:\n\t}"
        :: "r"(addr), "r"(parity) : "memory");
}
__device__ __forceinline__ void cp_async8(uint32_t saddr, const void* gaddr) {
    asm volatile("cp.async.ca.shared.global [%0], [%1], 8;"
                 :: "r"(saddr), "l"(gaddr) : "memory");
}
__device__ __forceinline__ void cp_commit() {
    asm volatile("cp.async.commit_group;" ::: "memory");
}
__device__ __forceinline__ void cp_wait2() {
    asm volatile("cp.async.wait_group 2;" ::: "memory");
}
#define CLUSTER_ARRIVE() asm volatile("barrier.cluster.arrive.aligned;" ::: "memory")
#define CLUSTER_WAIT()   asm volatile("barrier.cluster.wait.aligned;"   ::: "memory")

__global__ void __launch_bounds__(NTHR, 1) __cluster_dims__(CL, 1, 1)
rnn2d_kernel(const int* __restrict__ x,
             const float* __restrict__ Winh, const float* __restrict__ Winv,
             const float* __restrict__ Wch,  const float* __restrict__ bch,
             const float* __restrict__ Wcv,
             const float* __restrict__ Wout, const float* __restrict__ bout,
             float* __restrict__ out)
{
    extern __shared__ char smraw[];
    SM& sm = *reinterpret_cast<SM*>(smraw);
    const int tid = threadIdx.x;
    uint32_t rank;
    asm("mov.u32 %0, %%cluster_ctarank;" : "=r"(rank));
    const int grp = blockIdx.x >> 1;

    // ---------------- prologue ----------------
    for (int idx = tid; idx < 2 * UU; idx += NTHR) {
        ((float*)sm.winh)[idx] = Winh[idx];
        ((float*)sm.winv)[idx] = Winv[idx];
        ((float*)sm.wout)[idx] = Wout[idx];
    }
    for (int idx = tid; idx < UU; idx += NTHR) sm.bcarry[idx] = bch[idx];
    for (int idx = tid; idx < NB * LLATT * LLATT; idx += NTHR)
        ((int*)sm.xs)[idx] = x[grp * NB * LLATT * LLATT + idx];
    if (tid < NB) sm.logp[tid] = 0.f;
    if (tid == 0) {
        sm.bout0 = bout[0]; sm.bout1 = bout[1];
        mbar_init(smem_u32(&sm.bar1), 128);   // 128 writer arrivals from peer
    }
    __syncthreads();
    CLUSTER_ARRIVE(); CLUSTER_WAIT();          // publish mbarrier init

    const int khalf = tid >> 7;                // 0: k 0-255 (writers), 1: k 256-511
    const int tu    = tid & 127;
    const int ug0   = (int)rank * USL + 2 * tu;  // global unit pair

    const uint32_t bar_loc  = smem_u32(&sm.bar1);
    const uint32_t bar_rem  = mapa_rank(bar_loc, rank ^ 1u);
    const uint32_t hbuf_rem = mapa_rank(smem_u32(&sm.hbuf[0][0][0]), rank ^ 1u);
    const uint32_t st_rem   = mapa_rank(smem_u32(&sm.states[0][0][0]), rank ^ 1u);

    const float2* __restrict__ WchP =
        reinterpret_cast<const float2*>(Wch + (size_t)(khalf * 256) * UU + ug0);
    const float2* __restrict__ WcvP =
        reinterpret_cast<const float2*>(Wcv) + (int)rank * 128 + tu;
    // per-thread stage slots: wstage[s][q][tid]
    const uint32_t ws0 = smem_u32(&sm.wstage[0][0][tid]);

    int n = 0;
    for (int i = 0; i < LLATT; ++i) {
        const int d = (i & 1) ? -1 : 1;
        for (int j = 0; j < LLATT; ++j, ++n) {
            const int c   = (d == 1) ? j : (LLATT - 1 - j);
            const int buf = n & 1;

            // ---- half-row vertical GEMM events (31 total) ----
            if ((j == 8 && i < 15) || (j == 0 && i > 0)) {
                __syncthreads();
                const int i_src = (j == 8) ? i : i - 1;
                const int p0    = (j == 8) ? 0 : 8;
                ull A[8][2][2];
#pragma unroll
                for (int p = 0; p < 8; ++p)
#pragma unroll
                    for (int q = 0; q < 2; ++q) { A[p][q][0] = 0ull; A[p][q][1] = 0ull; }
                float2 wb[2][8];
#pragma unroll
                for (int q = 0; q < 8; ++q) wb[0][q] = WcvP[(khalf * 256 + q) * 256];
#pragma unroll 1
                for (int kk = 0; kk < 256; kk += 8) {
                    const int cb = (kk >> 3) & 1;
                    if (kk + 8 < 256) {
#pragma unroll
                        for (int q = 0; q < 8; ++q)
                            wb[cb ^ 1][q] = WcvP[(khalf * 256 + kk + 8 + q) * 256];
                    }
#pragma unroll
                    for (int q = 0; q < 8; ++q) {
                        const int k = khalf * 256 + kk + q;
                        const float2 w = wb[cb][q];
                        const ull wx = pk2(w.x, w.x);
                        const ull wy = pk2(w.y, w.y);
#pragma unroll
                        for (int p = 0; p < 8; ++p) {
                            const ulonglong2 sv = *(const ulonglong2*)&sm.states[p][k][0];
                            fma2(A[p][0][0], sv.x, wx); fma2(A[p][0][1], sv.y, wx);
                            fma2(A[p][1][0], sv.x, wy); fma2(A[p][1][1], sv.y, wy);
                        }
                    }
                }
                const int lu0 = 2 * tu;
                if (khalf == 0) {
#pragma unroll
                    for (int p = 0; p < 8; ++p) {
                        const int col = (i_src & 1) ? 15 - (p0 + p) : (p0 + p);
                        sm.vrow[col][lu0][0] = A[p][0][0];
                        sm.vrow[col][lu0][1] = A[p][0][1];
                        sm.vrow[col][lu0 + 1][0] = A[p][1][0];
                        sm.vrow[col][lu0 + 1][1] = A[p][1][1];
                    }
                }
                __syncthreads();
                if (khalf == 1) {
#pragma unroll
                    for (int p = 0; p < 8; ++p) {
                        const int col = (i_src & 1) ? 15 - (p0 + p) : (p0 + p);
                        sm.vrow[col][lu0][0] = add2(sm.vrow[col][lu0][0], A[p][0][0]);
                        sm.vrow[col][lu0][1] = add2(sm.vrow[col][lu0][1], A[p][0][1]);
                        sm.vrow[col][lu0 + 1][0] = add2(sm.vrow[col][lu0 + 1][0], A[p][1][0]);
                        sm.vrow[col][lu0 + 1][1] = add2(sm.vrow[col][lu0 + 1][1], A[p][1][1]);
                    }
                }
                __syncthreads();
                CLUSTER_ARRIVE(); CLUSTER_WAIT();   // fence GEMM vs slot reuse
            }

            // ---- h @ W_carry_h over my k-half: cp.async 3-stage pipeline ----
            ull a00 = 0ull, a01 = 0ull, a10 = 0ull, a11 = 0ull;
            if (j > 0) {
                const int kbase = khalf * 256;
                // prologue: stage chunks 0,1,2
#pragma unroll
                for (int s = 0; s < 3; ++s) {
#pragma unroll
                    for (int q = 0; q < 8; ++q)
                        cp_async8(ws0 + (uint32_t)((s * 8 + q) * 256 * 8),
                                  WchP + (s * 8 + q) * 256);
                    cp_commit();
                }
#pragma unroll 1
                for (int ck = 0; ck < 32; ++ck) {
                    cp_wait2();                      // chunk ck staged
                    const int s = ck - (ck / 3) * 3; // ck % 3
                    const float2* ws = &sm.wstage[s][0][tid];
#pragma unroll
                    for (int q = 0; q < 8; ++q) {
                        const int k = kbase + ck * 8 + q;
                        const ull h0 = sm.hbuf[buf ^ 1][k][0];
                        const ull h1 = sm.hbuf[buf ^ 1][k][1];
                        const float2 w = ws[q * 256];
                        const ull wx = pk2(w.x, w.x);
                        const ull wy = pk2(w.y, w.y);
                        fma2(a00, h0, wx); fma2(a01, h1, wx);
                        fma2(a10, h0, wy); fma2(a11, h1, wy);
                    }
                    if (ck + 3 < 32) {               // refill stage s with chunk ck+3
#pragma unroll
                        for (int q = 0; q < 8; ++q)
                            cp_async8(ws0 + (uint32_t)((s * 8 + q) * 256 * 8),
                                      WchP + ((ck + 3) * 8 + q) * 256);
                    }
                    cp_commit();                     // uniform group accounting
                }
            }
            if (khalf == 1) {
                sm.pred[tu][0][0] = a00; sm.pred[tu][0][1] = a01;
                sm.pred[tu][1][0] = a10; sm.pred[tu][1][1] = a11;
            }
            __syncthreads();   // S1: partials visible

            // ---- reduce + inputs + elu + distribute (threads 0-127) ----
            if (khalf == 0) {
                float v[2][4];
                upk2(a00, v[0][0], v[0][1]); upk2(a01, v[0][2], v[0][3]);
                upk2(a10, v[1][0], v[1][1]); upk2(a11, v[1][2], v[1][3]);
                if (j > 0) {
#pragma unroll
                    for (int q = 0; q < 2; ++q) {
                        float p0f, p1f;
                        upk2(sm.pred[tu][q][0], p0f, p1f);
                        v[q][0] += p0f; v[q][1] += p1f;
                        upk2(sm.pred[tu][q][1], p0f, p1f);
                        v[q][2] += p0f; v[q][3] += p1f;
                    }
                }
                if (i > 0) {
#pragma unroll
                    for (int q = 0; q < 2; ++q) {
                        float p0f, p1f;
                        upk2(sm.vrow[c][2 * tu + q][0], p0f, p1f);
                        v[q][0] += p0f; v[q][1] += p1f;
                        upk2(sm.vrow[c][2 * tu + q][1], p0f, p1f);
                        v[q][2] += p0f; v[q][3] += p1f;
                    }
                }
                int sh[NB], sv[NB];
                if (j > 0) {
                    const int cp = c - d;
#pragma unroll
                    for (int b = 0; b < NB; ++b) sh[b] = sm.xs[b][i * LLATT + cp];
                }
                if (i > 0) {
#pragma unroll
                    for (int b = 0; b < NB; ++b) sv[b] = sm.xs[b][(i - 1) * LLATT + c];
                }
                const int slot = j & 7;
#pragma unroll
                for (int q = 0; q < 2; ++q) {
                    const int u = ug0 + q;
                    const float base = sm.bcarry[u];
#pragma unroll
                    for (int b = 0; b < NB; ++b) {
                        float t = v[q][b] + base;
                        if (j > 0) t += sm.winh[sh[b]][u];
                        if (i > 0) t += sm.winv[sv[b]][u];
                        v[q][b] = t > 0.f ? t : expm1f(t);
                    }
                    const ull e0 = pk2(v[q][0], v[q][1]);
                    const ull e1 = pk2(v[q][2], v[q][3]);
                    sm.hbuf[buf][u][0] = e0;   sm.hbuf[buf][u][1] = e1;
                    sm.states[slot][u][0] = e0; sm.states[slot][u][1] = e1;
                    const uint32_t ho = (uint32_t)(((buf * UU + u) * 2) * 8);
                    st_cl64(hbuf_rem + ho,     e0);
                    st_cl64(hbuf_rem + ho + 8, e1);
                    const uint32_t so = (uint32_t)(((slot * UU + u) * 2) * 8);
                    st_cl64(st_rem + so,     e0);
                    st_cl64(st_rem + so + 8, e1);
                }
                mbar_arrive_remote(bar_rem);
            }
            __syncthreads();              // S2: local h visible
            mbar_wait_parity(bar_loc, (uint32_t)(n & 1));  // peer slice arrived

            // ---- logits: warp w -> (batch w>>1, class w&1), local full h ----
            {
                const int w = tid >> 5, lane = tid & 31;
                const int b = w >> 1, dc = w & 1;
                const int bp = b >> 1, hi = b & 1;
                float z = 0.f;
#pragma unroll
                for (int q = 0; q < 16; ++q) {
                    const int u = lane + q * 32;
                    float lo2, hi2;
                    upk2(sm.hbuf[buf][u][bp], lo2, hi2);
                    z += (hi ? hi2 : lo2) * sm.wout[u][dc];
                }
#pragma unroll
                for (int off = 16; off; off >>= 1)
                    z += __shfl_down_sync(0xffffffffu, z, off);
                if (lane == 0) sm.z[b][dc] = z;
            }
            __syncthreads();              // S3
            if (tid < NB) {
                const float z0 = sm.z[tid][0] + sm.bout0;
                const float z1 = sm.z[tid][1] + sm.bout1;
                const int s = sm.xs[tid][i * LLATT + c];
                const float m = fmaxf(z0, z1);
                const float lse = m + logf(expf(z0 - m) + expf(z1 - m));
                sm.logp[tid] += (s ? z1 : z0) - lse;
            }
        }
    }
    __syncthreads();
    if (rank == 0 && tid < NB) out[grp * NB + tid] = sm.logp[tid];
    CLUSTER_ARRIVE(); CLUSTER_WAIT();     // no CTA exits while peer may write DSMEM
}

extern "C" void kernel_launch(void* const* d_in, const int* in_sizes, int n_in,
                              void* d_out, int out_size)
{
    const int*   x    = (const int*)d_in[0];
    const float* Winh = (const float*)d_in[1];
    const float* Winv = (const float*)d_in[2];
    const float* Wch  = (const float*)d_in[3];
    const float* bch  = (const float*)d_in[4];
    const float* Wcv  = (const float*)d_in[5];
    const float* Wout = (const float*)d_in[6];
    const float* bout = (const float*)d_in[7];
    float* out = (float*)d_out;

    const int smem = (int)sizeof(SM);
    cudaFuncSetAttribute(rnn2d_kernel,
                         cudaFuncAttributeMaxDynamicSharedMemorySize, smem);
    rnn2d_kernel<<<NCTA, NTHR, smem>>>(x, Winh, Winv, Wch, bch, Wcv,
                                       Wout, bout, out);
}

// round 13
// speedup vs baseline: 1.4573x; 1.0006x over previous
#include <cuda_runtime.h>
#include <math.h>
#include <stdint.h>

#define LLATT 16
#define UU    512
#define NB    4            // batches per group
#define CL    2            // CTAs per cluster (unit split)
#define USL   256          // units per CTA
#define NTHR  256
#define NGRP  64
#define NCTA  128

typedef unsigned long long ull;

struct SM {
    ull    hbuf[2][UU][2];        // [buf][global unit][bpair]       16 KB
    ull    states[8][UU][2];      // last 8 scan positions            64 KB
    ull    vrow[LLATT][USL][2];   // vertical term per column         64 KB
    ull    pred[128][2][2];       // k-half partials                   4 KB
    float2 wstage[3][8][256];     // cp.async weight stages           48 KB
    float  winh[2][UU];
    float  winv[2][UU];
    float  wout[UU][2];
    float  bcarry[UU];
    float  z[NB][2];
    float  logp[NB];
    float  bout0, bout1;
    int    xs[NB][LLATT * LLATT];
    ull    bar1;
};

__device__ __forceinline__ ull pk2(float lo, float hi) {
    ull r; asm("mov.b64 %0, {%1, %2};" : "=l"(r) : "f"(lo), "f"(hi)); return r;
}
__device__ __forceinline__ void upk2(ull v, float& lo, float& hi) {
    asm("mov.b64 {%0, %1}, %2;" : "=f"(lo), "=f"(hi) : "l"(v));
}
__device__ __forceinline__ void fma2(ull& acc, ull a, ull b) {
    asm("fma.rn.f32x2 %0, %1, %2, %0;" : "+l"(acc) : "l"(a), "l"(b));
}
__device__ __forceinline__ ull add2(ull a, ull b) {
    ull r; asm("add.rn.f32x2 %0, %1, %2;" : "=l"(r) : "l"(a), "l"(b)); return r;
}
__device__ __forceinline__ uint32_t smem_u32(const void* p) {
    return (uint32_t)__cvta_generic_to_shared(p);
}
__device__ __forceinline__ uint32_t mapa_rank(uint32_t a, uint32_t r) {
    uint32_t o; asm("mapa.shared::cluster.u32 %0, %1, %2;" : "=r"(o) : "r"(a), "r"(r));
    return o;
}
__device__ __forceinline__ void st_cl64(uint32_t addr, ull v) {
    asm volatile("st.shared::cluster.b64 [%0], %1;" :: "r"(addr), "l"(v) : "memory");
}
__device__ __forceinline__ void mbar_init(uint32_t addr, uint32_t cnt) {
    asm volatile("mbarrier.init.shared.b64 [%0], %1;" :: "r"(addr), "r"(cnt) : "memory");
}
__device__ __forceinline__ void mbar_arrive_remote(uint32_t addr) {
    asm volatile("mbarrier.arrive.release.cluster.shared::cluster.b64 _, [%0];"
                 :: "r"(addr) : "memory");
}
__device__ __forceinline__ void mbar_wait_parity(uint32_t addr, uint32_t parity) {
    asm volatile(
        "{\n\t.reg .pred P;\n\t"
        "WLP_%=:\n\t"
        "mbarrier.try_wait.parity.acquire.cluster.shared::cta.b64 P, [%0], %1, 0x989680;\n\t"
        "@P bra.uni WDN_%=;\n\t"
        "bra.uni WLP_%=;\n\t"
        "WDN_%=:\n\t}"
        :: "r"(addr), "r"(parity) : "memory");
}
__device__ __forceinline__ void cp_async8(uint32_t saddr, const void* gaddr) {
    asm volatile("cp.async.ca.shared.global [%0], [%1], 8;"
                 :: "r"(saddr), "l"(gaddr) : "memory");
}
__device__ __forceinline__ void cp_commit() {
    asm volatile("cp.async.commit_group;" ::: "memory");
}
__device__ __forceinline__ void cp_wait2() {
    asm volatile("cp.async.wait_group 2;" ::: "memory");
}
#define CLUSTER_ARRIVE() asm volatile("barrier.cluster.arrive.aligned;" ::: "memory")
#define CLUSTER_WAIT()   asm volatile("barrier.cluster.wait.aligned;"   ::: "memory")

__global__ void __launch_bounds__(NTHR, 1) __cluster_dims__(CL, 1, 1)
rnn2d_kernel(const int* __restrict__ x,
             const float* __restrict__ Winh, const float* __restrict__ Winv,
             const float* __restrict__ Wch,  const float* __restrict__ bch,
             const float* __restrict__ Wcv,
             const float* __restrict__ Wout, const float* __restrict__ bout,
             float* __restrict__ out)
{
    extern __shared__ char smraw[];
    SM& sm = *reinterpret_cast<SM*>(smraw);
    const int tid = threadIdx.x;
    uint32_t rank;
    asm("mov.u32 %0, %%cluster_ctarank;" : "=r"(rank));
    const int grp = blockIdx.x >> 1;

    // ---------------- prologue ----------------
    for (int idx = tid; idx < 2 * UU; idx += NTHR) {
        ((float*)sm.winh)[idx] = Winh[idx];
        ((float*)sm.winv)[idx] = Winv[idx];
        ((float*)sm.wout)[idx] = Wout[idx];
    }
    for (int idx = tid; idx < UU; idx += NTHR) sm.bcarry[idx] = bch[idx];
    for (int idx = tid; idx < NB * LLATT * LLATT; idx += NTHR)
        ((int*)sm.xs)[idx] = x[grp * NB * LLATT * LLATT + idx];
    if (tid < NB) sm.logp[tid] = 0.f;
    if (tid == 0) {
        sm.bout0 = bout[0]; sm.bout1 = bout[1];
        mbar_init(smem_u32(&sm.bar1), 128);   // 128 writer arrivals from peer
    }
    __syncthreads();
    CLUSTER_ARRIVE(); CLUSTER_WAIT();          // publish mbarrier init

    const int khalf = tid >> 7;                // 0: k 0-255 (writers), 1: k 256-511
    const int tu    = tid & 127;
    const int ug0   = (int)rank * USL + 2 * tu;  // global unit pair

    const uint32_t bar_loc  = smem_u32(&sm.bar1);
    const uint32_t bar_rem  = mapa_rank(bar_loc, rank ^ 1u);
    const uint32_t hbuf_rem = mapa_rank(smem_u32(&sm.hbuf[0][0][0]), rank ^ 1u);
    const uint32_t st_rem   = mapa_rank(smem_u32(&sm.states[0][0][0]), rank ^ 1u);

    const float2* __restrict__ WchP =
        reinterpret_cast<const float2*>(Wch + (size_t)(khalf * 256) * UU + ug0);
    const float2* __restrict__ WcvP =
        reinterpret_cast<const float2*>(Wcv) + (int)rank * 128 + tu;
    // per-thread stage slots: wstage[s][q][tid]
    const uint32_t ws0 = smem_u32(&sm.wstage[0][0][tid]);

    int n = 0;
    for (int i = 0; i < LLATT; ++i) {
        const int d = (i & 1) ? -1 : 1;
        for (int j = 0; j < LLATT; ++j, ++n) {
            const int c   = (d == 1) ? j : (LLATT - 1 - j);
            const int buf = n & 1;

            // ---- half-row vertical GEMM events (31 total) ----
            if ((j == 8 && i < 15) || (j == 0 && i > 0)) {
                __syncthreads();
                const int i_src = (j == 8) ? i : i - 1;
                const int p0    = (j == 8) ? 0 : 8;
                ull A[8][2][2];
#pragma unroll
                for (int p = 0; p < 8; ++p)
#pragma unroll
                    for (int q = 0; q < 2; ++q) { A[p][q][0] = 0ull; A[p][q][1] = 0ull; }
                float2 wb[2][8];
#pragma unroll
                for (int q = 0; q < 8; ++q) wb[0][q] = WcvP[(khalf * 256 + q) * 256];
#pragma unroll 1
                for (int kk = 0; kk < 256; kk += 8) {
                    const int cb = (kk >> 3) & 1;
                    if (kk + 8 < 256) {
#pragma unroll
                        for (int q = 0; q < 8; ++q)
                            wb[cb ^ 1][q] = WcvP[(khalf * 256 + kk + 8 + q) * 256];
                    }
#pragma unroll
                    for (int q = 0; q < 8; ++q) {
                        const int k = khalf * 256 + kk + q;
                        const float2 w = wb[cb][q];
                        const ull wx = pk2(w.x, w.x);
                        const ull wy = pk2(w.y, w.y);
#pragma unroll
                        for (int p = 0; p < 8; ++p) {
                            const ulonglong2 sv = *(const ulonglong2*)&sm.states[p][k][0];
                            fma2(A[p][0][0], sv.x, wx); fma2(A[p][0][1], sv.y, wx);
                            fma2(A[p][1][0], sv.x, wy); fma2(A[p][1][1], sv.y, wy);
                        }
                    }
                }
                const int lu0 = 2 * tu;
                if (khalf == 0) {
#pragma unroll
                    for (int p = 0; p < 8; ++p) {
                        const int col = (i_src & 1) ? 15 - (p0 + p) : (p0 + p);
                        sm.vrow[col][lu0][0] = A[p][0][0];
                        sm.vrow[col][lu0][1] = A[p][0][1];
                        sm.vrow[col][lu0 + 1][0] = A[p][1][0];
                        sm.vrow[col][lu0 + 1][1] = A[p][1][1];
                    }
                }
                __syncthreads();
                if (khalf == 1) {
#pragma unroll
                    for (int p = 0; p < 8; ++p) {
                        const int col = (i_src & 1) ? 15 - (p0 + p) : (p0 + p);
                        sm.vrow[col][lu0][0] = add2(sm.vrow[col][lu0][0], A[p][0][0]);
                        sm.vrow[col][lu0][1] = add2(sm.vrow[col][lu0][1], A[p][0][1]);
                        sm.vrow[col][lu0 + 1][0] = add2(sm.vrow[col][lu0 + 1][0], A[p][1][0]);
                        sm.vrow[col][lu0 + 1][1] = add2(sm.vrow[col][lu0 + 1][1], A[p][1][1]);
                    }
                }
                __syncthreads();
                CLUSTER_ARRIVE(); CLUSTER_WAIT();   // fence GEMM vs slot reuse
            }

            // ---- h @ W_carry_h over my k-half: cp.async 3-stage pipeline ----
            ull a00 = 0ull, a01 = 0ull, a10 = 0ull, a11 = 0ull;
            if (j > 0) {
                const int kbase = khalf * 256;
                // prologue: stage chunks 0,1,2
#pragma unroll
                for (int s = 0; s < 3; ++s) {
#pragma unroll
                    for (int q = 0; q < 8; ++q)
                        cp_async8(ws0 + (uint32_t)((s * 8 + q) * 256 * 8),
                                  WchP + (s * 8 + q) * 256);
                    cp_commit();
                }
#pragma unroll 1
                for (int ck = 0; ck < 32; ++ck) {
                    cp_wait2();                      // chunk ck staged
                    const int s = ck - (ck / 3) * 3; // ck % 3
                    const float2* ws = &sm.wstage[s][0][tid];
#pragma unroll
                    for (int q = 0; q < 8; ++q) {
                        const int k = kbase + ck * 8 + q;
                        const ull h0 = sm.hbuf[buf ^ 1][k][0];
                        const ull h1 = sm.hbuf[buf ^ 1][k][1];
                        const float2 w = ws[q * 256];
                        const ull wx = pk2(w.x, w.x);
                        const ull wy = pk2(w.y, w.y);
                        fma2(a00, h0, wx); fma2(a01, h1, wx);
                        fma2(a10, h0, wy); fma2(a11, h1, wy);
                    }
                    if (ck + 3 < 32) {               // refill stage s with chunk ck+3
#pragma unroll
                        for (int q = 0; q < 8; ++q)
                            cp_async8(ws0 + (uint32_t)((s * 8 + q) * 256 * 8),
                                      WchP + ((ck + 3) * 8 + q) * 256);
                    }
                    cp_commit();                     // uniform group accounting
                }
            }
            if (khalf == 1) {
                sm.pred[tu][0][0] = a00; sm.pred[tu][0][1] = a01;
                sm.pred[tu][1][0] = a10; sm.pred[tu][1][1] = a11;
            }
            __syncthreads();   // S1: partials visible

            // ---- reduce + inputs + elu + distribute (threads 0-127) ----
            if (khalf == 0) {
                float v[2][4];
                upk2(a00, v[0][0], v[0][1]); upk2(a01, v[0][2], v[0][3]);
                upk2(a10, v[1][0], v[1][1]); upk2(a11, v[1][2], v[1][3]);
                if (j > 0) {
#pragma unroll
                    for (int q = 0; q < 2; ++q) {
                        float p0f, p1f;
                        upk2(sm.pred[tu][q][0], p0f, p1f);
                        v[q][0] += p0f; v[q][1] += p1f;
                        upk2(sm.pred[tu][q][1], p0f, p1f);
                        v[q][2] += p0f; v[q][3] += p1f;
                    }
                }
                if (i > 0) {
#pragma unroll
                    for (int q = 0; q < 2; ++q) {
                        float p0f, p1f;
                        upk2(sm.vrow[c][2 * tu + q][0], p0f, p1f);
                        v[q][0] += p0f; v[q][1] += p1f;
                        upk2(sm.vrow[c][2 * tu + q][1], p0f, p1f);
                        v[q][2] += p0f; v[q][3] += p1f;
                    }
                }
                int sh[NB], sv[NB];
                if (j > 0) {
                    const int cp = c - d;
#pragma unroll
                    for (int b = 0; b < NB; ++b) sh[b] = sm.xs[b][i * LLATT + cp];
                }
                if (i > 0) {
#pragma unroll
                    for (int b = 0; b < NB; ++b) sv[b] = sm.xs[b][(i - 1) * LLATT + c];
                }
                const int slot = j & 7;
#pragma unroll
                for (int q = 0; q < 2; ++q) {
                    const int u = ug0 + q;
                    const float base = sm.bcarry[u];
#pragma unroll
                    for (int b = 0; b < NB; ++b) {
                        float t = v[q][b] + base;
                        if (j > 0) t += sm.winh[sh[b]][u];
                        if (i > 0) t += sm.winv[sv[b]][u];
                        v[q][b] = t > 0.f ? t : expm1f(t);
                    }
                    const ull e0 = pk2(v[q][0], v[q][1]);
                    const ull e1 = pk2(v[q][2], v[q][3]);
                    sm.hbuf[buf][u][0] = e0;   sm.hbuf[buf][u][1] = e1;
                    sm.states[slot][u][0] = e0; sm.states[slot][u][1] = e1;
                    const uint32_t ho = (uint32_t)(((buf * UU + u) * 2) * 8);
                    st_cl64(hbuf_rem + ho,     e0);
                    st_cl64(hbuf_rem + ho + 8, e1);
                    const uint32_t so = (uint32_t)(((slot * UU + u) * 2) * 8);
                    st_cl64(st_rem + so,     e0);
                    st_cl64(st_rem + so + 8, e1);
                }
                mbar_arrive_remote(bar_rem);
            }
            __syncthreads();              // S2: local h visible
            mbar_wait_parity(bar_loc, (uint32_t)(n & 1));  // peer slice arrived

            // ---- logits: warp w -> (batch w>>1, class w&1), local full h ----
            {
                const int w = tid >> 5, lane = tid & 31;
                const int b = w >> 1, dc = w & 1;
                const int bp = b >> 1, hi = b & 1;
                float z = 0.f;
#pragma unroll
                for (int q = 0; q < 16; ++q) {
                    const int u = lane + q * 32;
                    float lo2, hi2;
                    upk2(sm.hbuf[buf][u][bp], lo2, hi2);
                    z += (hi ? hi2 : lo2) * sm.wout[u][dc];
                }
#pragma unroll
                for (int off = 16; off; off >>= 1)
                    z += __shfl_down_sync(0xffffffffu, z, off);
                if (lane == 0) sm.z[b][dc] = z;
            }
            __syncthreads();              // S3
            if (tid < NB) {
                const float z0 = sm.z[tid][0] + sm.bout0;
                const float z1 = sm.z[tid][1] + sm.bout1;
                const int s = sm.xs[tid][i * LLATT + c];
                const float m = fmaxf(z0, z1);
                const float lse = m + logf(expf(z0 - m) + expf(z1 - m));
                sm.logp[tid] += (s ? z1 : z0) - lse;
            }
        }
    }
    __syncthreads();
    if (rank == 0 && tid < NB) out[grp * NB + tid] = sm.logp[tid];
    CLUSTER_ARRIVE(); CLUSTER_WAIT();     // no CTA exits while peer may write DSMEM
}

extern "C" void kernel_launch(void* const* d_in, const int* in_sizes, int n_in,
                              void* d_out, int out_size)
{
    const int*   x    = (const int*)d_in[0];
    const float* Winh = (const float*)d_in[1];
    const float* Winv = (const float*)d_in[2];
    const float* Wch  = (const float*)d_in[3];
    const float* bch  = (const float*)d_in[4];
    const float* Wcv  = (const float*)d_in[5];
    const float* Wout = (const float*)d_in[6];
    const float* bout = (const float*)d_in[7];
    float* out = (float*)d_out;

    const int smem = (int)sizeof(SM);
    cudaFuncSetAttribute(rnn2d_kernel,
                         cudaFuncAttributeMaxDynamicSharedMemorySize, smem);
    rnn2d_kernel<<<NCTA, NTHR, smem>>>(x, Winh, Winv, Wch, bch, Wcv,
                                       Wout, bout, out);
}